// round 4
// baseline (speedup 1.0000x reference)
#include <cuda_runtime.h>

// Zero-initialized at module load; self-reset by the finalizing block each run.
__device__ unsigned int g_conf[25];
__device__ unsigned int g_done;

#define THREADS 256
#define GROUPS_PER_TILE 256            // one group (4 rows) per thread per tile

__device__ __forceinline__ int soft_pred(float x0, float x1, float x2, float x3, float x4) {
    float m = fmaxf(fmaxf(fmaxf(x0, x1), fmaxf(x2, x3)), x4);
    float e0 = __expf(x0 - m);
    float e1 = __expf(x1 - m);
    float e2 = __expf(x2 - m);
    float e3 = __expf(x3 - m);
    float e4 = __expf(x4 - m);
    float s  = e0 + e1 + e2 + e3 + e4;
    float sa = (e1 + 2.0f * e2 + 3.0f * e3 + 4.0f * e4) / s;
    int p = __float2int_rn(sa);        // round half-to-even, matches jnp.round
    return max(0, min(4, p));
}

__global__ void __launch_bounds__(THREADS, 4)
kappa_fused_kernel(const float* __restrict__ preds,
                   const int* __restrict__ labels,
                   float* __restrict__ out,
                   int n) {
    __shared__ float4 s4[GROUPS_PER_TILE * 5];     // 20 KB staging tile
    __shared__ unsigned int sconf[25];
    __shared__ unsigned int s_is_last;

    if (threadIdx.x < 25) sconf[threadIdx.x] = 0u;
    __syncthreads();

    const int groups   = n >> 2;                   // 4 rows per group
    const int numTiles = (groups + GROUPS_PER_TILE - 1) / GROUPS_PER_TILE;
    const float4* __restrict__ p4 = reinterpret_cast<const float4*>(preds);
    const int4*   __restrict__ t4 = reinterpret_cast<const int4*>(labels);

    for (int tile = blockIdx.x; tile < numTiles; tile += gridDim.x) {
        const int gBase      = tile * GROUPS_PER_TILE;
        const int tileGroups = min(GROUPS_PER_TILE, groups - gBase);
        const int nVec       = tileGroups * 5;

        // Stage: perfectly coalesced consecutive float4 loads.
        const size_t srcBase = (size_t)gBase * 5;
        #pragma unroll 5
        for (int i = threadIdx.x; i < nVec; i += THREADS)
            s4[i] = p4[srcBase + i];
        __syncthreads();

        if (threadIdx.x < tileGroups) {
            const float4* r = &s4[threadIdx.x * 5];   // conflict-free LDS.128 phases
            float4 a = r[0], b = r[1], c = r[2], d = r[3], e = r[4];
            int4 t = t4[gBase + threadIdx.x];          // coalesced

            int p0 = soft_pred(a.x, a.y, a.z, a.w, b.x);
            int p1 = soft_pred(b.y, b.z, b.w, c.x, c.y);
            int p2 = soft_pred(c.z, c.w, d.x, d.y, d.z);
            int p3 = soft_pred(d.w, e.x, e.y, e.z, e.w);

            atomicAdd(&sconf[t.x * 5 + p0], 1u);
            atomicAdd(&sconf[t.y * 5 + p1], 1u);
            atomicAdd(&sconf[t.z * 5 + p2], 1u);
            atomicAdd(&sconf[t.w * 5 + p3], 1u);
        }
        __syncthreads();
    }

    // Flush block-local counts to global.
    if (threadIdx.x < 25) {
        unsigned int v = sconf[threadIdx.x];
        if (v) atomicAdd(&g_conf[threadIdx.x], v);
    }
    __threadfence();
    __syncthreads();

    // Last block to finish runs the epilogue and self-resets the globals.
    if (threadIdx.x == 0)
        s_is_last = (atomicAdd(&g_done, 1u) == gridDim.x - 1u) ? 1u : 0u;
    __syncthreads();

    if (s_is_last && threadIdx.x == 0) {
        __threadfence();
        double cf[25];
        #pragma unroll
        for (int i = 0; i < 25; ++i) {
            cf[i] = (double)(*(volatile unsigned int*)&g_conf[i]);
            g_conf[i] = 0u;                       // reset for next graph replay
        }
        g_done = 0u;

        // Tail rows (n % 4), serial — at most 3 rows.
        for (int i = (groups << 2); i < n; ++i) {
            const float* rr = preds + (size_t)i * 5;
            int p = soft_pred(rr[0], rr[1], rr[2], rr[3], rr[4]);
            cf[labels[i] * 5 + p] += 1.0;
        }

        double th[5] = {0, 0, 0, 0, 0}, ph[5] = {0, 0, 0, 0, 0};
        #pragma unroll
        for (int i = 0; i < 5; ++i)
            #pragma unroll
            for (int j = 0; j < 5; ++j) {
                th[i] += cf[i * 5 + j];
                ph[j] += cf[i * 5 + j];
            }
        double num = 0.0, den = 0.0;
        #pragma unroll
        for (int i = 0; i < 5; ++i)
            #pragma unroll
            for (int j = 0; j < 5; ++j) {
                double w = (double)((i - j) * (i - j)) * (1.0 / 16.0);
                num += cf[i * 5 + j] * w;
                den += th[i] * ph[j] * w;
            }
        // (num/N) / (den/N^2) = num * N / den
        out[0] = (float)(num * (double)n / den);
    }
}

extern "C" void kernel_launch(void* const* d_in, const int* in_sizes, int n_in,
                              void* d_out, int out_size) {
    const float* preds  = (const float*)d_in[0];
    const int*   labels = (const int*)d_in[1];
    const int n = in_sizes[1];

    const int groups   = n >> 2;
    const int numTiles = (groups + GROUPS_PER_TILE - 1) / GROUPS_PER_TILE;
    int blocks = 148 * 4;                       // matches __launch_bounds__ residency
    if (blocks > numTiles) blocks = numTiles;
    if (blocks < 1) blocks = 1;

    kappa_fused_kernel<<<blocks, THREADS>>>(preds, labels, (float*)d_out, n);
}

// round 5
// speedup vs baseline: 1.0111x; 1.0111x over previous
#include <cuda_runtime.h>
#include <cstdint>

// Zero-initialized at module load; self-reset by the finalizing block each run.
__device__ unsigned int g_conf[25];
__device__ unsigned int g_done;

#define THREADS 256
#define GROUPS_PER_TILE 256        // one group (4 rows = 5 float4 + 1 int4) per thread

__device__ __forceinline__ void cp_async16(void* smem_dst, const void* gmem_src) {
    uint32_t s = (uint32_t)__cvta_generic_to_shared(smem_dst);
    asm volatile("cp.async.cg.shared.global [%0], [%1], 16;" :: "r"(s), "l"(gmem_src));
}
__device__ __forceinline__ void cp_async_commit() {
    asm volatile("cp.async.commit_group;" ::: "memory");
}
template <int N>
__device__ __forceinline__ void cp_async_wait() {
    asm volatile("cp.async.wait_group %0;" :: "n"(N) : "memory");
}

__device__ __forceinline__ int soft_pred(float x0, float x1, float x2, float x3, float x4) {
    float m = fmaxf(fmaxf(fmaxf(x0, x1), fmaxf(x2, x3)), x4);
    float e0 = __expf(x0 - m);
    float e1 = __expf(x1 - m);
    float e2 = __expf(x2 - m);
    float e3 = __expf(x3 - m);
    float e4 = __expf(x4 - m);
    float s  = e0 + e1 + e2 + e3 + e4;
    float sa = (e1 + 2.0f * e2 + 3.0f * e3 + 4.0f * e4) / s;
    int p = __float2int_rn(sa);    // round half-to-even, matches jnp.round
    return max(0, min(4, p));
}

__global__ void __launch_bounds__(THREADS, 4)
kappa_pipe_kernel(const float* __restrict__ preds,
                  const int* __restrict__ labels,
                  float* __restrict__ out,
                  int n) {
    // Double-buffered staging: preds 2x20KB, labels 2x4KB, total ~48KB.
    __shared__ float4 sp[2][GROUPS_PER_TILE * 5];
    __shared__ int4   sl[2][GROUPS_PER_TILE];
    __shared__ unsigned int sconf[25];
    __shared__ unsigned int s_is_last;

    if (threadIdx.x < 25) sconf[threadIdx.x] = 0u;
    __syncthreads();

    const int groups   = n >> 2;
    const int numTiles = (groups + GROUPS_PER_TILE - 1) / GROUPS_PER_TILE;
    const float4* __restrict__ p4 = reinterpret_cast<const float4*>(preds);
    const int4*   __restrict__ t4 = reinterpret_cast<const int4*>(labels);
    const int tid = threadIdx.x;

    // Prefetch helper (inlined manually): stage tile `t` into buffer `b`.
    auto prefetch = [&](int t, int b) {
        const int gBase      = t * GROUPS_PER_TILE;
        const int tileGroups = min(GROUPS_PER_TILE, groups - gBase);
        const int nVec       = tileGroups * 5;
        const size_t srcBase = (size_t)gBase * 5;
        #pragma unroll 5
        for (int i = tid; i < nVec; i += THREADS)
            cp_async16(&sp[b][i], &p4[srcBase + i]);
        if (tid < tileGroups)
            cp_async16(&sl[b][tid], &t4[gBase + tid]);
    };

    int t = blockIdx.x;            // grid is clamped to <= numTiles
    prefetch(t, 0);
    cp_async_commit();

    int buf = 0;
    for (; t < numTiles; t += gridDim.x) {
        const int tn = t + gridDim.x;
        if (tn < numTiles) prefetch(tn, buf ^ 1);
        cp_async_commit();         // commit even if empty: keeps group counting uniform
        cp_async_wait<1>();        // tile t's group complete
        __syncthreads();

        const int tileGroups = min(GROUPS_PER_TILE, groups - t * GROUPS_PER_TILE);
        if (tid < tileGroups) {
            const float4* r = &sp[buf][tid * 5];   // conflict-free LDS.128 phases
            float4 a = r[0], b4 = r[1], c = r[2], d = r[3], e = r[4];
            int4 lb = sl[buf][tid];

            int p0 = soft_pred(a.x,  a.y,  a.z,  a.w,  b4.x);
            int p1 = soft_pred(b4.y, b4.z, b4.w, c.x,  c.y);
            int p2 = soft_pred(c.z,  c.w,  d.x,  d.y,  d.z);
            int p3 = soft_pred(d.w,  e.x,  e.y,  e.z,  e.w);

            atomicAdd(&sconf[lb.x * 5 + p0], 1u);
            atomicAdd(&sconf[lb.y * 5 + p1], 1u);
            atomicAdd(&sconf[lb.z * 5 + p2], 1u);
            atomicAdd(&sconf[lb.w * 5 + p3], 1u);
        }
        __syncthreads();           // buffer safe to overwrite next iteration
        buf ^= 1;
    }

    // Flush block-local counts to global.
    if (tid < 25) {
        unsigned int v = sconf[tid];
        if (v) atomicAdd(&g_conf[tid], v);
    }
    __threadfence();
    __syncthreads();

    // Last block to finish runs the epilogue and self-resets the globals.
    if (tid == 0)
        s_is_last = (atomicAdd(&g_done, 1u) == gridDim.x - 1u) ? 1u : 0u;
    __syncthreads();

    if (s_is_last && tid == 0) {
        __threadfence();
        double cf[25];
        #pragma unroll
        for (int i = 0; i < 25; ++i) {
            cf[i] = (double)(*(volatile unsigned int*)&g_conf[i]);
            g_conf[i] = 0u;        // reset for next graph replay
        }
        g_done = 0u;

        // Tail rows (n % 4), at most 3, handled serially.
        for (int i = (groups << 2); i < n; ++i) {
            const float* rr = preds + (size_t)i * 5;
            int p = soft_pred(rr[0], rr[1], rr[2], rr[3], rr[4]);
            cf[labels[i] * 5 + p] += 1.0;
        }

        double th[5] = {0, 0, 0, 0, 0}, ph[5] = {0, 0, 0, 0, 0};
        #pragma unroll
        for (int i = 0; i < 5; ++i)
            #pragma unroll
            for (int j = 0; j < 5; ++j) {
                th[i] += cf[i * 5 + j];
                ph[j] += cf[i * 5 + j];
            }
        double num = 0.0, den = 0.0;
        #pragma unroll
        for (int i = 0; i < 5; ++i)
            #pragma unroll
            for (int j = 0; j < 5; ++j) {
                double w = (double)((i - j) * (i - j)) * (1.0 / 16.0);
                num += cf[i * 5 + j] * w;
                den += th[i] * ph[j] * w;
            }
        // (num/N) / (den/N^2) = num * N / den
        out[0] = (float)(num * (double)n / den);
    }
}

extern "C" void kernel_launch(void* const* d_in, const int* in_sizes, int n_in,
                              void* d_out, int out_size) {
    const float* preds  = (const float*)d_in[0];
    const int*   labels = (const int*)d_in[1];
    const int n = in_sizes[1];

    const int groups   = n >> 2;
    const int numTiles = (groups + GROUPS_PER_TILE - 1) / GROUPS_PER_TILE;
    int blocks = 148 * 4;          // matches __launch_bounds__ residency
    if (blocks > numTiles) blocks = numTiles;
    if (blocks < 1) blocks = 1;

    kappa_pipe_kernel<<<blocks, THREADS>>>(preds, labels, (float*)d_out, n);
}

// round 6
// speedup vs baseline: 1.0499x; 1.0384x over previous
#include <cuda_runtime.h>
#include <cstdint>

// Zero-initialized at module load; self-reset by the finalizing block each run.
__device__ unsigned int g_conf[25];
__device__ unsigned int g_done;

#define THREADS 256
#define GROUPS_PER_TILE 256     // one group (4 rows = 5 float4 + 1 int4) per thread
#define PRED_TILE_BYTES (GROUPS_PER_TILE * 80)   // 20480
#define LBL_TILE_BYTES  (GROUPS_PER_TILE * 16)   // 4096

__device__ __forceinline__ uint32_t smem_u32(const void* p) {
    return (uint32_t)__cvta_generic_to_shared(p);
}

__device__ __forceinline__ void mbar_init(uint32_t mbar, uint32_t count) {
    asm volatile("mbarrier.init.shared.b64 [%0], %1;" :: "r"(mbar), "r"(count) : "memory");
}
__device__ __forceinline__ void mbar_expect_tx(uint32_t mbar, uint32_t bytes) {
    asm volatile("mbarrier.arrive.expect_tx.shared.b64 _, [%0], %1;"
                 :: "r"(mbar), "r"(bytes) : "memory");
}
__device__ __forceinline__ void mbar_wait(uint32_t mbar, uint32_t parity) {
    asm volatile(
        "{\n\t"
        ".reg .pred P;\n\t"
        "WAIT_%=:\n\t"
        "mbarrier.try_wait.parity.acquire.cta.shared::cta.b64 P, [%0], %1, 0x989680;\n\t"
        "@P bra.uni DONE_%=;\n\t"
        "bra.uni WAIT_%=;\n\t"
        "DONE_%=:\n\t"
        "}" :: "r"(mbar), "r"(parity) : "memory");
}
__device__ __forceinline__ void bulk_g2s(uint32_t smem_dst, const void* gmem_src,
                                         uint32_t bytes, uint32_t mbar) {
    asm volatile(
        "cp.async.bulk.shared::cta.global.mbarrier::complete_tx::bytes [%0], [%1], %2, [%3];"
        :: "r"(smem_dst), "l"(gmem_src), "r"(bytes), "r"(mbar) : "memory");
}

__device__ __forceinline__ int soft_pred(float x0, float x1, float x2, float x3, float x4) {
    float m = fmaxf(fmaxf(fmaxf(x0, x1), fmaxf(x2, x3)), x4);
    float e0 = __expf(x0 - m);
    float e1 = __expf(x1 - m);
    float e2 = __expf(x2 - m);
    float e3 = __expf(x3 - m);
    float e4 = __expf(x4 - m);
    float s  = e0 + e1 + e2 + e3 + e4;
    float sa = (e1 + 2.0f * e2 + 3.0f * e3 + 4.0f * e4) / s;
    int p = __float2int_rn(sa);  // round half-to-even, matches jnp.round
    return max(0, min(4, p));
}

__global__ void __launch_bounds__(THREADS, 4)
kappa_tma_kernel(const float* __restrict__ preds,
                 const int* __restrict__ labels,
                 float* __restrict__ out,
                 int n) {
    __shared__ alignas(16) float4 sp[2][GROUPS_PER_TILE * 5];  // 2 x 20 KB
    __shared__ alignas(16) int4   sl[2][GROUPS_PER_TILE];      // 2 x 4 KB
    __shared__ alignas(8)  uint64_t mbar_s[2];
    __shared__ unsigned int sconf[25];
    __shared__ unsigned int s_is_last;

    const int tid = threadIdx.x;
    if (tid < 25) sconf[tid] = 0u;
    if (tid == 0) {
        mbar_init(smem_u32(&mbar_s[0]), 1);
        mbar_init(smem_u32(&mbar_s[1]), 1);
    }
    __syncthreads();

    const int groups   = n >> 2;
    const int numTiles = (groups + GROUPS_PER_TILE - 1) / GROUPS_PER_TILE;
    const char* __restrict__ pbase = reinterpret_cast<const char*>(preds);
    const char* __restrict__ lbase = reinterpret_cast<const char*>(labels);

    // Issue tile t's bulk copies into buffer b (tid 0 only).
    auto prefetch = [&](int t, int b) {
        const int gBase      = t * GROUPS_PER_TILE;
        const int tileGroups = min(GROUPS_PER_TILE, groups - gBase);
        const uint32_t bp = (uint32_t)tileGroups * 80u;
        const uint32_t bl = (uint32_t)tileGroups * 16u;
        const uint32_t mb = smem_u32(&mbar_s[b]);
        mbar_expect_tx(mb, bp + bl);
        bulk_g2s(smem_u32(&sp[b][0]), pbase + (size_t)gBase * 80u, bp, mb);
        bulk_g2s(smem_u32(&sl[b][0]), lbase + (size_t)gBase * 16u, bl, mb);
    };

    int t = blockIdx.x;             // grid clamped to <= numTiles
    if (tid == 0) prefetch(t, 0);

    int buf = 0;
    uint32_t ph[2] = {0u, 0u};
    for (; t < numTiles; t += gridDim.x) {
        const int tn = t + gridDim.x;
        if (tn < numTiles && tid == 0) prefetch(tn, buf ^ 1);

        mbar_wait(smem_u32(&mbar_s[buf]), ph[buf]);
        ph[buf] ^= 1u;

        const int tileGroups = min(GROUPS_PER_TILE, groups - t * GROUPS_PER_TILE);
        if (tid < tileGroups) {
            const float4* r = &sp[buf][tid * 5];   // conflict-free LDS.128 phases
            float4 a = r[0], b4 = r[1], c = r[2], d = r[3], e = r[4];
            int4 lb = sl[buf][tid];

            int p0 = soft_pred(a.x,  a.y,  a.z,  a.w,  b4.x);
            int p1 = soft_pred(b4.y, b4.z, b4.w, c.x,  c.y);
            int p2 = soft_pred(c.z,  c.w,  d.x,  d.y,  d.z);
            int p3 = soft_pred(d.w,  e.x,  e.y,  e.z,  e.w);

            atomicAdd(&sconf[lb.x * 5 + p0], 1u);
            atomicAdd(&sconf[lb.y * 5 + p1], 1u);
            atomicAdd(&sconf[lb.z * 5 + p2], 1u);
            atomicAdd(&sconf[lb.w * 5 + p3], 1u);
        }
        __syncthreads();             // buffer consumed; safe to refill next round
        buf ^= 1;
    }

    // Flush block-local counts to global.
    if (tid < 25) {
        unsigned int v = sconf[tid];
        if (v) atomicAdd(&g_conf[tid], v);
    }
    __threadfence();
    __syncthreads();

    // Last block to finish runs the epilogue and self-resets the globals.
    if (tid == 0)
        s_is_last = (atomicAdd(&g_done, 1u) == gridDim.x - 1u) ? 1u : 0u;
    __syncthreads();

    if (s_is_last && tid == 0) {
        __threadfence();
        double cf[25];
        #pragma unroll
        for (int i = 0; i < 25; ++i) {
            cf[i] = (double)(*(volatile unsigned int*)&g_conf[i]);
            g_conf[i] = 0u;          // reset for next graph replay
        }
        g_done = 0u;

        // Tail rows (n % 4), at most 3, handled serially (none when n % 4 == 0).
        for (int i = (groups << 2); i < n; ++i) {
            const float* rr = preds + (size_t)i * 5;
            int p = soft_pred(rr[0], rr[1], rr[2], rr[3], rr[4]);
            cf[labels[i] * 5 + p] += 1.0;
        }

        double th[5] = {0, 0, 0, 0, 0}, ph5[5] = {0, 0, 0, 0, 0};
        #pragma unroll
        for (int i = 0; i < 5; ++i)
            #pragma unroll
            for (int j = 0; j < 5; ++j) {
                th[i]  += cf[i * 5 + j];
                ph5[j] += cf[i * 5 + j];
            }
        double num = 0.0, den = 0.0;
        #pragma unroll
        for (int i = 0; i < 5; ++i)
            #pragma unroll
            for (int j = 0; j < 5; ++j) {
                double w = (double)((i - j) * (i - j)) * (1.0 / 16.0);
                num += cf[i * 5 + j] * w;
                den += th[i] * ph5[j] * w;
            }
        // (num/N) / (den/N^2) = num * N / den
        out[0] = (float)(num * (double)n / den);
    }
}

extern "C" void kernel_launch(void* const* d_in, const int* in_sizes, int n_in,
                              void* d_out, int out_size) {
    const float* preds  = (const float*)d_in[0];
    const int*   labels = (const int*)d_in[1];
    const int n = in_sizes[1];

    const int groups   = n >> 2;
    const int numTiles = (groups + GROUPS_PER_TILE - 1) / GROUPS_PER_TILE;
    int blocks = 148 * 4;            // matches __launch_bounds__ residency
    if (blocks > numTiles) blocks = numTiles;
    if (blocks < 1) blocks = 1;

    kappa_tma_kernel<<<blocks, THREADS>>>(preds, labels, (float*)d_out, n);
}